// round 14
// baseline (speedup 1.0000x reference)
#include <cuda_runtime.h>
#include <cuda_fp16.h>
#include <cstdint>

// GraphSAGE 2-layer, D=64 — persistent kernel <<<148, 1024>>>:
//   half-warp padded-CSR gather (fp16 rows, 8-deep pipelined)
//   + fp16 mma.sync combine  out = [feat|mean] @ [Wself;Wneigh] + b
//
// Feature table g_A[MAXN+1 rows][128 cols] fp16:
//   cols 0..63  = features (x for layer 1, h1 after combine1)
//   cols 64..127= neighbor mean (written by gather each layer)
//   row n       = all-zero sentinel for padded CSR edges
//
// Phase plan (8 grid barriers total -> even flip count, replay-safe):
//   P0 conv x->g_A (+zero row n) MERGED WITH hist(+rank)   [g_cnt pre-zeroed]
//   P1 scan(2a)  P2 base+pad(2b)  P3 fill  P4 gather1  P5 combine1(relu,->g_A)
//   P6 gather2   P7 combine2(->out fp32) + re-zero g_cnt for next launch
//   tail barrier (parity)

#define D 64
#define AC 128
#define MAXN 50048
#define MAXEP 1200000
#define NBLK 148
#define NTHR 1024
#define NWARP (NTHR / 32)
#define BSTRIDE 136

__device__ __half g_A[MAXN * AC];
__device__ int    g_cnt[MAXN];          // zero-init at module load; kernel restores
__device__ int    g_rowstart[MAXN];
__device__ int    g_rank[MAXEP];
__device__ int    g_edge[MAXEP];
__device__ int    g_part[NBLK];
__device__ unsigned g_bar_count;
__device__ volatile unsigned g_bar_sense;

// Sense-reversing grid barrier (validated R8-R13). Flip count per launch EVEN.
__device__ __forceinline__ void grid_barrier(unsigned& sense) {
    __syncthreads();
    if (threadIdx.x == 0) {
        sense ^= 1u;
        __threadfence();
        unsigned arrived = atomicAdd(&g_bar_count, 1u) + 1u;
        if (arrived == NBLK) {
            g_bar_count = 0;
            __threadfence();
            g_bar_sense = sense;
        } else {
            while (g_bar_sense != sense) __nanosleep(32);
        }
        __threadfence();
    }
    __syncthreads();
}

__device__ __forceinline__ void mma16816(float d[4],
                                         uint32_t a0, uint32_t a1,
                                         uint32_t a2, uint32_t a3,
                                         uint32_t b0, uint32_t b1) {
    asm volatile(
        "mma.sync.aligned.m16n8k16.row.col.f32.f16.f16.f32 "
        "{%0,%1,%2,%3}, {%4,%5,%6,%7}, {%8,%9}, {%0,%1,%2,%3};"
        : "+f"(d[0]), "+f"(d[1]), "+f"(d[2]), "+f"(d[3])
        : "r"(a0), "r"(a1), "r"(a2), "r"(a3), "r"(b0), "r"(b1));
}

// ---------------------------------------------------------------------------
// Gather: HALF-WARP per node, fp16 rows from g_A cols 0..63, 8-deep pipeline,
// next-stripe index prefetch, sentinel row n. Writes MEAN to cols 64..127.
// ---------------------------------------------------------------------------
__device__ void gather_phase(int n) {
    const uint2* __restrict__ base = reinterpret_cast<const uint2*>(g_A);
    const int nhw = NBLK * (NTHR / 16);
    const int ghw = blockIdx.x * (NTHR / 16) + (threadIdx.x >> 4);
    const int lane = threadIdx.x & 15;

    for (int node = ghw; node < n; node += nhw) {
        int start = g_rowstart[node];
        int cnt   = g_cnt[node];
        int degp  = (cnt + 7) & ~7;

        float a0 = 0.f, a1 = 0.f, a2 = 0.f, a3 = 0.f;
        const int* ep = g_edge + start;

        if (degp > 0) {
            int idx[8];
#pragma unroll
            for (int u = 0; u < 8; u++) idx[u] = __ldg(ep + u);

            for (int j = 0; j < degp; j += 8) {
                uint2 v[8];
#pragma unroll
                for (int u = 0; u < 8; u++)
                    v[u] = __ldg(base + (size_t)idx[u] * 32 + lane);

                bool more = (j + 8) < degp;
                int nidx[8];
#pragma unroll
                for (int u = 0; u < 8; u++)
                    nidx[u] = more ? __ldg(ep + j + 8 + u) : 0;

#pragma unroll
                for (int u = 0; u < 8; u++) {
                    float2 fa = __half22float2(
                        *reinterpret_cast<__half2*>(&v[u].x));
                    float2 fb = __half22float2(
                        *reinterpret_cast<__half2*>(&v[u].y));
                    a0 += fa.x; a1 += fa.y; a2 += fb.x; a3 += fb.y;
                }
#pragma unroll
                for (int u = 0; u < 8; u++) idx[u] = nidx[u];
            }
        }

        float inv = 1.0f / fmaxf((float)cnt, 1.0f);
        __half2 m0 = __floats2half2_rn(a0 * inv, a1 * inv);
        __half2 m1 = __floats2half2_rn(a2 * inv, a3 * inv);
        uint2 mw;
        mw.x = *reinterpret_cast<unsigned*>(&m0);
        mw.y = *reinterpret_cast<unsigned*>(&m1);
        *reinterpret_cast<uint2*>(
            const_cast<uint2*>(base) + (size_t)node * 32 + 16 + lane) = mw;
    }
}

// ---------------------------------------------------------------------------
// Combine via mma.sync: warp = one 16-node tile, N=64, K=128.
// ---------------------------------------------------------------------------
template <bool RELU, bool OUT16>
__device__ void combine_phase(const float* __restrict__ Wself,
                              const float* __restrict__ Wneigh,
                              const float* __restrict__ bias,
                              float* __restrict__ out, int n,
                              __half* sB) {
    const int t = threadIdx.x;
    for (int i = t; i < D * D; i += NTHR) {
        int k = i >> 6, nn = i & 63;
        sB[nn * BSTRIDE + k]      = __float2half(__ldg(Wself + i));
        sB[nn * BSTRIDE + 64 + k] = __float2half(__ldg(Wneigh + i));
    }
    __syncthreads();

    const int wid  = t >> 5;
    const int lane = t & 31;
    const int g  = lane >> 2;
    const int tg = lane & 3;

    const int ntiles = (n + 15) >> 4;
    const int tile = blockIdx.x * NWARP + wid;
    if (tile < ntiles) {
        const int node0 = tile << 4;
        const int r0 = node0 + g;
        const int r1 = node0 + g + 8;
        const int ra = (r0 < n) ? r0 : n;
        const int rb = (r1 < n) ? r1 : n;

        float dacc[8][4];
#pragma unroll
        for (int nb = 0; nb < 8; nb++) {
            int c0 = nb * 8 + tg * 2;
            float bz0 = __ldg(bias + c0);
            float bz1 = __ldg(bias + c0 + 1);
            dacc[nb][0] = bz0; dacc[nb][1] = bz1;
            dacc[nb][2] = bz0; dacc[nb][3] = bz1;
        }

        const __half* Ar0 = g_A + (size_t)ra * AC;
        const __half* Ar1 = g_A + (size_t)rb * AC;

#pragma unroll
        for (int kc = 0; kc < 8; kc++) {
            int kb = kc * 16;
            const __half* pa = Ar0 + kb + tg * 2;
            const __half* pb = Ar1 + kb + tg * 2;
            uint32_t a0 = *reinterpret_cast<const uint32_t*>(pa);
            uint32_t a1 = *reinterpret_cast<const uint32_t*>(pb);
            uint32_t a2 = *reinterpret_cast<const uint32_t*>(pa + 8);
            uint32_t a3 = *reinterpret_cast<const uint32_t*>(pb + 8);
#pragma unroll
            for (int nb = 0; nb < 8; nb++) {
                const __half* bp = sB + (nb * 8 + g) * BSTRIDE + kb + tg * 2;
                uint32_t b0 = *reinterpret_cast<const uint32_t*>(bp);
                uint32_t b1 = *reinterpret_cast<const uint32_t*>(bp + 8);
                mma16816(dacc[nb], a0, a1, a2, a3, b0, b1);
            }
        }

#pragma unroll
        for (int nb = 0; nb < 8; nb++) {
            int c0 = nb * 8 + tg * 2;
            float v0 = dacc[nb][0], v1 = dacc[nb][1];
            float v2 = dacc[nb][2], v3 = dacc[nb][3];
            if (RELU) {
                v0 = fmaxf(v0, 0.f); v1 = fmaxf(v1, 0.f);
                v2 = fmaxf(v2, 0.f); v3 = fmaxf(v3, 0.f);
            }
            if (OUT16) {
                __half2 h01 = __floats2half2_rn(v0, v1);
                __half2 h23 = __floats2half2_rn(v2, v3);
                if (r0 < n)
                    *reinterpret_cast<__half2*>(
                        g_A + (size_t)r0 * AC + c0) = h01;
                if (r1 < n)
                    *reinterpret_cast<__half2*>(
                        g_A + (size_t)r1 * AC + c0) = h23;
            } else {
                if (r0 < n)
                    *reinterpret_cast<float2*>(
                        out + (size_t)r0 * D + c0) = make_float2(v0, v1);
                if (r1 < n)
                    *reinterpret_cast<float2*>(
                        out + (size_t)r1 * D + c0) = make_float2(v2, v3);
            }
        }
    }
    __syncthreads();
}

// ---------------------------------------------------------------------------
__global__ void __launch_bounds__(NTHR, 1)
sage_kernel(const float* __restrict__ x,
            const int* __restrict__ src,
            const int* __restrict__ dst,
            const float* __restrict__ W1s, const float* __restrict__ W1n,
            const float* __restrict__ b1,
            const float* __restrict__ W2s, const float* __restrict__ W2n,
            const float* __restrict__ b2,
            float* __restrict__ out, int n, int E) {
    __shared__ __half sB[D * BSTRIDE];
    __shared__ int    sScan[NTHR];
    __shared__ int    sPart[NBLK];

    unsigned sense = 0;
    const int tid_g = blockIdx.x * NTHR + threadIdx.x;
    const int gstride = NBLK * NTHR;
    const int t = threadIdx.x;

    // ---- P0: conv x -> g_A cols 0..63 (+zero row n)  MERGED WITH  hist ----
    // g_cnt is all-zero on entry (module-load zero-init; phase 7 restores it).
    {
        int total16 = n * 16;
        for (int i = tid_g; i < total16; i += gstride) {
            int row = i >> 4, c4 = (i & 15) * 4;
            float4 v = reinterpret_cast<const float4*>(x)[i];
            __half2 h0 = __floats2half2_rn(v.x, v.y);
            __half2 h1 = __floats2half2_rn(v.z, v.w);
            uint2 w;
            w.x = *reinterpret_cast<unsigned*>(&h0);
            w.y = *reinterpret_cast<unsigned*>(&h1);
            *reinterpret_cast<uint2*>(g_A + (size_t)row * AC + c4) = w;
        }
        if (blockIdx.x == 0 && t < AC / 2) {
            __half2 z = __floats2half2_rn(0.f, 0.f);
            reinterpret_cast<__half2*>(g_A + (size_t)n * AC)[t] = z;
        }
        for (int e = tid_g; e < E; e += gstride)
            g_rank[e] = atomicAdd(&g_cnt[__ldg(dst + e)], 1);
    }
    grid_barrier(sense);                                   // 1

    // ---- P1: block-local exclusive scan of padded counts ----
    const int chunk = (n + NBLK - 1) / NBLK;
    const int node = blockIdx.x * chunk + t;
    int padded = 0;
    if (t < chunk && node < n) padded = (g_cnt[node] + 7) & ~7;
    sScan[t] = padded;
    __syncthreads();
    for (int off = 1; off < NTHR; off <<= 1) {
        int v = (t >= off) ? sScan[t - off] : 0;
        __syncthreads();
        sScan[t] += v;
        __syncthreads();
    }
    int excl = sScan[t] - padded;
    if (t == NTHR - 1) g_part[blockIdx.x] = sScan[NTHR - 1];
    grid_barrier(sense);                                   // 2

    // ---- P2: global base + rowstart + sentinel padding edges ----
    {
        if (t < NBLK) sPart[t] = g_part[t];
        __syncthreads();
        int base = 0;
        for (int b = 0; b < blockIdx.x; b++) base += sPart[b];
        if (t < chunk && node < n) {
            int rs = base + excl;
            g_rowstart[node] = rs;
            int cnt = g_cnt[node];
            int degp = (cnt + 7) & ~7;
            for (int j = cnt; j < degp; j++) g_edge[rs + j] = n;
        }
    }
    grid_barrier(sense);                                   // 3

    // ---- P3: fill CSR (atomic-free) ----
    for (int e = tid_g; e < E; e += gstride) {
        int d = __ldg(dst + e);
        g_edge[g_rowstart[d] + g_rank[e]] = __ldg(src + e);
    }
    grid_barrier(sense);                                   // 4

    // ---- P4: gather layer 1 ----
    gather_phase(n);
    grid_barrier(sense);                                   // 5

    // ---- P5: combine layer 1 (relu) -> h1 fp16 into g_A ----
    combine_phase<true, true>(W1s, W1n, b1, nullptr, n, sB);
    grid_barrier(sense);                                   // 6

    // ---- P6: gather layer 2 ----
    gather_phase(n);
    grid_barrier(sense);                                   // 7

    // ---- P7: combine layer 2 -> out fp32; restore g_cnt = 0 ----
    combine_phase<false, false>(W2s, W2n, b2, out, n, sB);
    for (int i = tid_g; i < n; i += gstride) g_cnt[i] = 0;
    grid_barrier(sense);                                   // 8 (parity)
}

// ---------------------------------------------------------------------------
extern "C" void kernel_launch(void* const* d_in, const int* in_sizes, int n_in,
                              void* d_out, int out_size) {
    const float* x        = (const float*)d_in[0];
    const int*   src      = (const int*)d_in[1];
    const int*   dst      = (const int*)d_in[2];
    const float* W1_self  = (const float*)d_in[3];
    const float* W1_neigh = (const float*)d_in[4];
    const float* b1       = (const float*)d_in[5];
    const float* W2_self  = (const float*)d_in[6];
    const float* W2_neigh = (const float*)d_in[7];
    const float* b2       = (const float*)d_in[8];
    float* out = (float*)d_out;

    int n = in_sizes[0] / D;
    int E = in_sizes[1];

    sage_kernel<<<NBLK, NTHR>>>(x, src, dst,
                                W1_self, W1_neigh, b1,
                                W2_self, W2_neigh, b2,
                                out, n, E);
}

// round 15
// speedup vs baseline: 1.0225x; 1.0225x over previous
#include <cuda_runtime.h>
#include <cuda_fp16.h>
#include <cstdint>

// GraphSAGE 2-layer, D=64 — persistent kernel <<<148, 768>>> (R13 structure):
//   half-warp padded-CSR gather (fp16 rows, 8-deep pipelined)
//   + fp16 mma.sync combine  out = [feat|mean] @ [Wself;Wneigh] + b
//   + R15: 8-deep batched hist & fill loops (MLP 8 on the CSR build).
//
// Feature table g_A[MAXN+1 rows][128 cols] fp16:
//   cols 0..63  = features (x for layer 1, h1 after combine1)
//   cols 64..127= neighbor mean (written by gather each layer)
//   row n       = all-zero sentinel for padded CSR edges
//
// Phases / 8 grid barriers:
//   0 conv+zero | 1 hist(+rank) | 2a scan | 2b base+pad
//   3 fill | 4 gather1 | 5 combine1(relu,->g_A) | 6 gather2 | 7 combine2(->out)

#define D 64
#define AC 128
#define MAXN 50048
#define MAXEP 1200000
#define NBLK 148
#define NTHR 768
#define NWARP (NTHR / 32)
#define BSTRIDE 136

__device__ __half g_A[MAXN * AC];
__device__ int    g_cnt[MAXN];
__device__ int    g_rowstart[MAXN];
__device__ int    g_rank[MAXEP];
__device__ int    g_edge[MAXEP];
__device__ int    g_part[NBLK];
__device__ unsigned g_bar_count;
__device__ volatile unsigned g_bar_sense;

// Sense-reversing grid barrier (validated R8-R14). Even flip count per launch.
__device__ __forceinline__ void grid_barrier(unsigned& sense) {
    __syncthreads();
    if (threadIdx.x == 0) {
        sense ^= 1u;
        __threadfence();
        unsigned arrived = atomicAdd(&g_bar_count, 1u) + 1u;
        if (arrived == NBLK) {
            g_bar_count = 0;
            __threadfence();
            g_bar_sense = sense;
        } else {
            while (g_bar_sense != sense) __nanosleep(32);
        }
        __threadfence();
    }
    __syncthreads();
}

__device__ __forceinline__ void mma16816(float d[4],
                                         uint32_t a0, uint32_t a1,
                                         uint32_t a2, uint32_t a3,
                                         uint32_t b0, uint32_t b1) {
    asm volatile(
        "mma.sync.aligned.m16n8k16.row.col.f32.f16.f16.f32 "
        "{%0,%1,%2,%3}, {%4,%5,%6,%7}, {%8,%9}, {%0,%1,%2,%3};"
        : "+f"(d[0]), "+f"(d[1]), "+f"(d[2]), "+f"(d[3])
        : "r"(a0), "r"(a1), "r"(a2), "r"(a3), "r"(b0), "r"(b1));
}

// ---------------------------------------------------------------------------
// Gather: HALF-WARP per node, fp16 rows from g_A cols 0..63, 8-deep pipeline,
// next-stripe index prefetch, sentinel row n. Writes MEAN to cols 64..127.
// ---------------------------------------------------------------------------
__device__ void gather_phase(int n) {
    const uint2* __restrict__ base = reinterpret_cast<const uint2*>(g_A);
    const int nhw = NBLK * (NTHR / 16);
    const int ghw = blockIdx.x * (NTHR / 16) + (threadIdx.x >> 4);
    const int lane = threadIdx.x & 15;

    for (int node = ghw; node < n; node += nhw) {
        int start = g_rowstart[node];
        int cnt   = g_cnt[node];
        int degp  = (cnt + 7) & ~7;

        float a0 = 0.f, a1 = 0.f, a2 = 0.f, a3 = 0.f;
        const int* ep = g_edge + start;

        if (degp > 0) {
            int idx[8];
#pragma unroll
            for (int u = 0; u < 8; u++) idx[u] = __ldg(ep + u);

            for (int j = 0; j < degp; j += 8) {
                uint2 v[8];
#pragma unroll
                for (int u = 0; u < 8; u++)
                    v[u] = __ldg(base + (size_t)idx[u] * 32 + lane);

                bool more = (j + 8) < degp;
                int nidx[8];
#pragma unroll
                for (int u = 0; u < 8; u++)
                    nidx[u] = more ? __ldg(ep + j + 8 + u) : 0;

#pragma unroll
                for (int u = 0; u < 8; u++) {
                    float2 fa = __half22float2(
                        *reinterpret_cast<__half2*>(&v[u].x));
                    float2 fb = __half22float2(
                        *reinterpret_cast<__half2*>(&v[u].y));
                    a0 += fa.x; a1 += fa.y; a2 += fb.x; a3 += fb.y;
                }
#pragma unroll
                for (int u = 0; u < 8; u++) idx[u] = nidx[u];
            }
        }

        float inv = 1.0f / fmaxf((float)cnt, 1.0f);
        __half2 m0 = __floats2half2_rn(a0 * inv, a1 * inv);
        __half2 m1 = __floats2half2_rn(a2 * inv, a3 * inv);
        uint2 mw;
        mw.x = *reinterpret_cast<unsigned*>(&m0);
        mw.y = *reinterpret_cast<unsigned*>(&m1);
        *reinterpret_cast<uint2*>(
            const_cast<uint2*>(base) + (size_t)node * 32 + 16 + lane) = mw;
    }
}

// ---------------------------------------------------------------------------
// Combine via mma.sync: warp = one 16-node tile, N=64, K=128.
// ---------------------------------------------------------------------------
template <bool RELU, bool OUT16>
__device__ void combine_phase(const float* __restrict__ Wself,
                              const float* __restrict__ Wneigh,
                              const float* __restrict__ bias,
                              float* __restrict__ out, int n,
                              __half* sB) {
    const int t = threadIdx.x;
    for (int i = t; i < D * D; i += NTHR) {
        int k = i >> 6, nn = i & 63;
        sB[nn * BSTRIDE + k]      = __float2half(__ldg(Wself + i));
        sB[nn * BSTRIDE + 64 + k] = __float2half(__ldg(Wneigh + i));
    }
    __syncthreads();

    const int wid  = t >> 5;
    const int lane = t & 31;
    const int g  = lane >> 2;
    const int tg = lane & 3;

    const int ntiles = (n + 15) >> 4;
    const int tile = blockIdx.x * NWARP + wid;
    if (tile < ntiles) {
        const int node0 = tile << 4;
        const int r0 = node0 + g;
        const int r1 = node0 + g + 8;
        const int ra = (r0 < n) ? r0 : n;
        const int rb = (r1 < n) ? r1 : n;

        float dacc[8][4];
#pragma unroll
        for (int nb = 0; nb < 8; nb++) {
            int c0 = nb * 8 + tg * 2;
            float bz0 = __ldg(bias + c0);
            float bz1 = __ldg(bias + c0 + 1);
            dacc[nb][0] = bz0; dacc[nb][1] = bz1;
            dacc[nb][2] = bz0; dacc[nb][3] = bz1;
        }

        const __half* Ar0 = g_A + (size_t)ra * AC;
        const __half* Ar1 = g_A + (size_t)rb * AC;

#pragma unroll
        for (int kc = 0; kc < 8; kc++) {
            int kb = kc * 16;
            const __half* pa = Ar0 + kb + tg * 2;
            const __half* pb = Ar1 + kb + tg * 2;
            uint32_t a0 = *reinterpret_cast<const uint32_t*>(pa);
            uint32_t a1 = *reinterpret_cast<const uint32_t*>(pb);
            uint32_t a2 = *reinterpret_cast<const uint32_t*>(pa + 8);
            uint32_t a3 = *reinterpret_cast<const uint32_t*>(pb + 8);
#pragma unroll
            for (int nb = 0; nb < 8; nb++) {
                const __half* bp = sB + (nb * 8 + g) * BSTRIDE + kb + tg * 2;
                uint32_t b0 = *reinterpret_cast<const uint32_t*>(bp);
                uint32_t b1 = *reinterpret_cast<const uint32_t*>(bp + 8);
                mma16816(dacc[nb], a0, a1, a2, a3, b0, b1);
            }
        }

#pragma unroll
        for (int nb = 0; nb < 8; nb++) {
            int c0 = nb * 8 + tg * 2;
            float v0 = dacc[nb][0], v1 = dacc[nb][1];
            float v2 = dacc[nb][2], v3 = dacc[nb][3];
            if (RELU) {
                v0 = fmaxf(v0, 0.f); v1 = fmaxf(v1, 0.f);
                v2 = fmaxf(v2, 0.f); v3 = fmaxf(v3, 0.f);
            }
            if (OUT16) {
                __half2 h01 = __floats2half2_rn(v0, v1);
                __half2 h23 = __floats2half2_rn(v2, v3);
                if (r0 < n)
                    *reinterpret_cast<__half2*>(
                        g_A + (size_t)r0 * AC + c0) = h01;
                if (r1 < n)
                    *reinterpret_cast<__half2*>(
                        g_A + (size_t)r1 * AC + c0) = h23;
            } else {
                if (r0 < n)
                    *reinterpret_cast<float2*>(
                        out + (size_t)r0 * D + c0) = make_float2(v0, v1);
                if (r1 < n)
                    *reinterpret_cast<float2*>(
                        out + (size_t)r1 * D + c0) = make_float2(v2, v3);
            }
        }
    }
    __syncthreads();
}

// ---------------------------------------------------------------------------
__global__ void __launch_bounds__(NTHR)
sage_kernel(const float* __restrict__ x,
            const int* __restrict__ src,
            const int* __restrict__ dst,
            const float* __restrict__ W1s, const float* __restrict__ W1n,
            const float* __restrict__ b1,
            const float* __restrict__ W2s, const float* __restrict__ W2n,
            const float* __restrict__ b2,
            float* __restrict__ out, int n, int E) {
    __shared__ __half sB[D * BSTRIDE];
    __shared__ int    sScan[NTHR];
    __shared__ int    sPart[NBLK];

    unsigned sense = 0;
    const int tid_g = blockIdx.x * NTHR + threadIdx.x;
    const int gstride = NBLK * NTHR;
    const int t = threadIdx.x;

    // ---- P0: x -> g_A cols 0..63 (fp16), zero row n, zero counters ----
    {
        int total16 = n * 16;
        for (int i = tid_g; i < total16; i += gstride) {
            int row = i >> 4, c4 = (i & 15) * 4;
            float4 v = reinterpret_cast<const float4*>(x)[i];
            __half2 h0 = __floats2half2_rn(v.x, v.y);
            __half2 h1 = __floats2half2_rn(v.z, v.w);
            uint2 w;
            w.x = *reinterpret_cast<unsigned*>(&h0);
            w.y = *reinterpret_cast<unsigned*>(&h1);
            *reinterpret_cast<uint2*>(g_A + (size_t)row * AC + c4) = w;
        }
        for (int i = tid_g; i < n; i += gstride) g_cnt[i] = 0;
        if (blockIdx.x == 0 && t < AC / 2) {
            __half2 z = __floats2half2_rn(0.f, 0.f);
            reinterpret_cast<__half2*>(g_A + (size_t)n * AC)[t] = z;
        }
    }
    grid_barrier(sense);                                   // 1

    // ---- P1: histogram + rank capture (8-deep batched) ----
    {
        int e = tid_g;
        while (e + 7 * gstride < E) {
            int dv[8];
#pragma unroll
            for (int u = 0; u < 8; u++) dv[u] = __ldg(dst + e + u * gstride);
#pragma unroll
            for (int u = 0; u < 8; u++)
                g_rank[e + u * gstride] = atomicAdd(&g_cnt[dv[u]], 1);
            e += 8 * gstride;
        }
        for (; e < E; e += gstride)
            g_rank[e] = atomicAdd(&g_cnt[__ldg(dst + e)], 1);
    }
    grid_barrier(sense);                                   // 2

    // ---- P2a: block-local exclusive scan of padded counts ----
    const int chunk = (n + NBLK - 1) / NBLK;
    const int node = blockIdx.x * chunk + t;
    int padded = 0;
    if (t < chunk && node < n) padded = (g_cnt[node] + 7) & ~7;
    sScan[t] = padded;
    __syncthreads();
    for (int off = 1; off < NTHR; off <<= 1) {
        int v = (t >= off) ? sScan[t - off] : 0;
        __syncthreads();
        sScan[t] += v;
        __syncthreads();
    }
    int excl = sScan[t] - padded;
    if (t == NTHR - 1) g_part[blockIdx.x] = sScan[NTHR - 1];
    grid_barrier(sense);                                   // 3

    // ---- P2b: global base + rowstart + sentinel padding edges ----
    {
        if (t < NBLK) sPart[t] = g_part[t];
        __syncthreads();
        int base = 0;
        for (int b = 0; b < blockIdx.x; b++) base += sPart[b];
        if (t < chunk && node < n) {
            int rs = base + excl;
            g_rowstart[node] = rs;
            int cnt = g_cnt[node];
            int degp = (cnt + 7) & ~7;
            for (int j = cnt; j < degp; j++) g_edge[rs + j] = n;
        }
    }
    grid_barrier(sense);                                   // 4

    // ---- P3: fill CSR (atomic-free, 8-deep batched) ----
    {
        int e = tid_g;
        while (e + 7 * gstride < E) {
            int dv[8], rv[8], sv[8], rs[8];
#pragma unroll
            for (int u = 0; u < 8; u++) {
                dv[u] = __ldg(dst + e + u * gstride);
                rv[u] = __ldg(g_rank + e + u * gstride);
                sv[u] = __ldg(src + e + u * gstride);
            }
#pragma unroll
            for (int u = 0; u < 8; u++) rs[u] = __ldg(g_rowstart + dv[u]);
#pragma unroll
            for (int u = 0; u < 8; u++) g_edge[rs[u] + rv[u]] = sv[u];
            e += 8 * gstride;
        }
        for (; e < E; e += gstride) {
            int d = __ldg(dst + e);
            g_edge[g_rowstart[d] + g_rank[e]] = __ldg(src + e);
        }
    }
    grid_barrier(sense);                                   // 5

    // ---- P4: gather layer 1 ----
    gather_phase(n);
    grid_barrier(sense);                                   // 6

    // ---- P5: combine layer 1 (relu) -> h1 fp16 into g_A ----
    combine_phase<true, true>(W1s, W1n, b1, nullptr, n, sB);
    grid_barrier(sense);                                   // 7

    // ---- P6: gather layer 2 ----
    gather_phase(n);
    grid_barrier(sense);                                   // 8

    // ---- P7: combine layer 2 -> out fp32 ----
    combine_phase<false, false>(W2s, W2n, b2, out, n, sB);
}

// ---------------------------------------------------------------------------
extern "C" void kernel_launch(void* const* d_in, const int* in_sizes, int n_in,
                              void* d_out, int out_size) {
    const float* x        = (const float*)d_in[0];
    const int*   src      = (const int*)d_in[1];
    const int*   dst      = (const int*)d_in[2];
    const float* W1_self  = (const float*)d_in[3];
    const float* W1_neigh = (const float*)d_in[4];
    const float* b1       = (const float*)d_in[5];
    const float* W2_self  = (const float*)d_in[6];
    const float* W2_neigh = (const float*)d_in[7];
    const float* b2       = (const float*)d_in[8];
    float* out = (float*)d_out;

    int n = in_sizes[0] / D;
    int E = in_sizes[1];

    sage_kernel<<<NBLK, NTHR>>>(x, src, dst,
                                W1_self, W1_neigh, b1,
                                W2_self, W2_neigh, b2,
                                out, n, E);
}